// round 15
// baseline (speedup 1.0000x reference)
#include <cuda_runtime.h>
#include <cuda_fp16.h>
#include <cstdint>

// ---------------- problem constants ------------------------------------------
#define B_ 4
#define S_ 2048
#define D_ 512
#define H_ 8
#define NT 8192               // B*S tokens
#define DH 4096               // D*H
#define ZN 32                 // B*H attention instances
#define ATT_SCALE 0.04419417382415922f   // 512^-0.5

// ---------------- scratch (device globals; no runtime allocation) -------------
__device__ __half g_xn[(size_t)NT * D_];               // 8 MB
__device__ __half g_q[(size_t)ZN * S_ * D_];           // 64 MB [z][s][d] (pre-scaled)
__device__ __half g_k[(size_t)ZN * S_ * D_];           // 64 MB [z][s][d]
__device__ __half g_vt[(size_t)ZN * S_ * D_];          // 64 MB [z][d][s]
__device__ __half g_p[(size_t)ZN * S_ * S_];           // 256 MB fp16 exp(logits)
__device__ float  g_partial[(size_t)ZN * S_ * 32];     // 8 MB per-row partial sums
__device__ __half g_attn[(size_t)NT * DH];             // 64 MB [token][h*512+d]
__device__ __half g_wtq[(size_t)DH * D_];              // 4 MB  W^T [4096][512]
__device__ __half g_wtk[(size_t)DH * D_];
__device__ __half g_wtv[(size_t)DH * D_];
__device__ __half g_wto[(size_t)D_ * DH];              // 4 MB  o_w^T [512][4096]

// ---------------- helpers -----------------------------------------------------
__device__ __forceinline__ uint32_t smem_u32(const void* p) {
    uint32_t a;
    asm("{ .reg .u64 t; cvta.to.shared.u64 t, %1; cvt.u32.u64 %0, t; }" : "=r"(a) : "l"(p));
    return a;
}
__device__ __forceinline__ void cp16(uint32_t dst, const void* src) {
    asm volatile("cp.async.cg.shared.global [%0], [%1], 16;" :: "r"(dst), "l"(src));
}
#define CP_COMMIT() asm volatile("cp.async.commit_group;")
#define CP_WAIT1()  asm volatile("cp.async.wait_group 1;")

__device__ __forceinline__ void ldsm_x4(uint32_t* r, uint32_t addr) {
    asm volatile("ldmatrix.sync.aligned.m8n8.x4.shared.b16 {%0,%1,%2,%3}, [%4];"
        : "=r"(r[0]), "=r"(r[1]), "=r"(r[2]), "=r"(r[3]) : "r"(addr));
}
__device__ __forceinline__ void mma_f16(float* c, const uint32_t* a, const uint32_t* b) {
    asm volatile(
        "mma.sync.aligned.m16n8k16.row.col.f32.f16.f16.f32 "
        "{%0,%1,%2,%3}, {%4,%5,%6,%7}, {%8,%9}, {%0,%1,%2,%3};"
        : "+f"(c[0]), "+f"(c[1]), "+f"(c[2]), "+f"(c[3])
        : "r"(a[0]), "r"(a[1]), "r"(a[2]), "r"(a[3]), "r"(b[0]), "r"(b[1]));
}

// ---------------- LayerNorm (fp32 in -> fp16 out) -----------------------------
__global__ void ln_kernel(const float* __restrict__ x,
                          const float* __restrict__ w,
                          const float* __restrict__ b) {
    int row = blockIdx.x;
    int t = threadIdx.x;                       // 128 threads, 4 floats each
    const float4* xr = (const float4*)(x + (size_t)row * D_);
    float4 v = xr[t];
    float s  = v.x + v.y + v.z + v.w;
    float q  = v.x * v.x + v.y * v.y + v.z * v.z + v.w * v.w;
#pragma unroll
    for (int o = 16; o > 0; o >>= 1) {
        s += __shfl_xor_sync(0xffffffffu, s, o);
        q += __shfl_xor_sync(0xffffffffu, q, o);
    }
    __shared__ float ss[4], sq[4];
    int wid = t >> 5;
    if ((t & 31) == 0) { ss[wid] = s; sq[wid] = q; }
    __syncthreads();
    s = ss[0] + ss[1] + ss[2] + ss[3];
    q = sq[0] + sq[1] + sq[2] + sq[3];
    float mu  = s * (1.0f / D_);
    float var = q * (1.0f / D_) - mu * mu;
    float r   = rsqrtf(var + 1e-5f);
    float4 wv = ((const float4*)w)[t];
    float4 bv = ((const float4*)b)[t];
    __half2 h0 = __floats2half2_rn((v.x - mu) * r * wv.x + bv.x,
                                   (v.y - mu) * r * wv.y + bv.y);
    __half2 h1 = __floats2half2_rn((v.z - mu) * r * wv.z + bv.z,
                                   (v.w - mu) * r * wv.w + bv.w);
    __half2* dst = (__half2*)(g_xn + (size_t)row * D_);
    dst[2 * t]     = h0;
    dst[2 * t + 1] = h1;
}

// ---------------- merged 32x32 weight transposes (fp32 in -> half out) --------
__global__ void transpose_all(const float* __restrict__ qw, const float* __restrict__ kw,
                              const float* __restrict__ vw, const float* __restrict__ ow) {
    __shared__ float tile[32][33];
    int sel = blockIdx.x >> 11;                  // 0..3
    int id  = blockIdx.x & 2047;
    const float* in;
    __half* out;
    int R, C, bx, by;
    if (sel < 3) {
        in = (sel == 0) ? qw : (sel == 1) ? kw : vw;
        out = (sel == 0) ? g_wtq : (sel == 1) ? g_wtk : g_wtv;
        R = 512; C = 4096;
        bx = id & 127; by = id >> 7;             // 128 x 16
    } else {
        in = ow; out = g_wto;
        R = 4096; C = 512;
        bx = id & 15; by = id >> 4;              // 16 x 128
    }

    int x  = bx * 32 + threadIdx.x;
    int y0 = by * 32;
#pragma unroll
    for (int j = 0; j < 32; j += 8)
        tile[threadIdx.y + j][threadIdx.x] = in[(size_t)(y0 + threadIdx.y + j) * C + x];
    __syncthreads();
    int ox  = y0 + threadIdx.x;
    int oy0 = bx * 32;
#pragma unroll
    for (int j = 0; j < 32; j += 8)
        out[(size_t)(oy0 + threadIdx.y + j) * R + ox] =
            __float2half_rn(tile[threadIdx.x][threadIdx.y + j]);
}

// ---------------- fp16 mma.sync GEMM ------------------------------------------
// 128x128 CTA tile, 128 threads = 4 warps (2x2), warp tile 64x64.
// 5 stages x 32-deep, TWO stages consumed per wait+barrier (halved sync
// overhead, 32-deep stages and >=1-iteration prefetch slack preserved).
// Double-buffered ldmatrix fragments throughout.
// MODE 0: g_xn @ Wt(which from bid)^T -> q(/scale)/k half; V -> g_vt DIRECTLY
// MODE 1: Qs @ K^T -> exp -> g_p fp16 + row partial sums (per z)
// MODE 2: E @ Vt^T * (1/rowsum from g_partial, prologue-fused) -> g_attn
// MODE 3: g_attn @ Wto^T     -> out fp32 (+bias)
constexpr int STG = 5;
constexpr int ROWB = 80;                         // 32 halves (64B) + 16B pad
constexpr int OPBYTES = 128 * ROWB;              // one operand tile: 10240 B
constexpr int STGBYTES = 2 * OPBYTES;            // A+B per stage: 20480 B
constexpr int PIPEBYTES = STG * STGBYTES;        // 102400 B
constexpr int GEMM_SMEM = PIPEBYTES + 512;       // + sh_inv[128] for MODE 2

template <int MODE>
__global__ __launch_bounds__(128, 2)
void gemm_tc(const float* __restrict__ bias0, const float* __restrict__ bias1,
             const float* __restrict__ bias2, float* __restrict__ Cout) {
    constexpr int K   = (MODE == 0) ? 512 : (MODE == 1) ? 512 : (MODE == 2) ? 2048 : 4096;
    constexpr int lda = (MODE == 2) ? 2048 : (MODE == 3) ? 4096 : 512;
    constexpr int ldb = (MODE == 2) ? 2048 : (MODE == 3) ? 4096 : 512;
    constexpr int TI  = K / 64;                  // iterations (2 stages each)
    constexpr int NST = K / 32;                  // total 32-deep stages

    extern __shared__ __half sh[];
    uint32_t sbase = smem_u32(sh);
    float* sh_inv = (float*)((char*)sh + PIPEBYTES);

    int tid = threadIdx.x;
    int lane = tid & 31, wid = tid >> 5;       // 4 warps
    int warp_m = wid & 1, warp_n = wid >> 1;   // 2 x 2 -> 64 x 64 per warp

    int which = 0, m0, n0, z = 0;
    if (MODE == 0) {                 // merged QKV: 1D grid of 6144
        which = blockIdx.x >> 11;
        int id = blockIdx.x & 2047;
        n0 = (id & 31) * 128;
        m0 = (id >> 5) * 128;
    } else {
        n0 = blockIdx.x * 128;
        m0 = blockIdx.y * 128;
        z  = blockIdx.z;
    }
    const float* bias = (MODE == 0)
        ? (which == 0 ? bias0 : which == 1 ? bias1 : bias2) : bias0;

    const __half* A;
    const __half* Bm;
    if (MODE == 0)      { A = g_xn;
                          Bm = (which == 0) ? g_wtq : (which == 1) ? g_wtk : g_wtv; }
    else if (MODE == 1) { A = g_q + (size_t)z * S_ * D_; Bm = g_k + (size_t)z * S_ * D_; }
    else if (MODE == 2) { A = g_p + ((size_t)z << 22);   Bm = g_vt + (size_t)z * S_ * D_; }
    else                { A = g_attn; Bm = g_wto; }
    A  += (size_t)m0 * lda;
    Bm += (size_t)n0 * ldb;

    float c[4][8][4];
#pragma unroll
    for (int i = 0; i < 4; i++)
#pragma unroll
        for (int j = 0; j < 8; j++)
#pragma unroll
            for (int e = 0; e < 4; e++) c[i][j][e] = 0.0f;

    // tile fill: 128 rows x 32 halves per operand = 512 x 16B each; 4+4 per thread
    int lrow = tid >> 2, lseg = tid & 3;       // lrow 0..31
    auto tile_load = [&](int stg, int k0) {
        uint32_t abase = sbase + (uint32_t)stg * STGBYTES;
        uint32_t bbase = abase + OPBYTES;
        uint32_t off = (uint32_t)lrow * ROWB + (uint32_t)lseg * 16;
#pragma unroll
        for (int i = 0; i < 4; i++) {
            cp16(abase + off + (uint32_t)i * 32 * ROWB,
                 A + (size_t)(lrow + i * 32) * lda + k0 + lseg * 8);
            cp16(bbase + off + (uint32_t)i * 32 * ROWB,
                 Bm + (size_t)(lrow + i * 32) * ldb + k0 + lseg * 8);
        }
        CP_COMMIT();
    };

    // ldmatrix lane geometry
    int rowA = warp_m * 64 + (lane & 7) + ((lane & 8) ? 8 : 0);
    int kA   = (lane & 16) ? 8 : 0;
    int rowB = warp_n * 64 + (lane & 7) + ((lane & 16) ? 8 : 0);
    int kB   = (lane & 8) ? 8 : 0;

    uint32_t a0[4][4], b0[4][4], a1[4][4], b1[4][4];   // double-buffered frags

    auto ld_frags = [&](uint32_t base, int kf, uint32_t a[4][4], uint32_t b[4][4]) {
        uint32_t koffA = (uint32_t)(kA + kf * 16) * 2;
        uint32_t koffB = (uint32_t)(kB + kf * 16) * 2;
        uint32_t bb = base + OPBYTES;
#pragma unroll
        for (int im = 0; im < 4; im++)
            ldsm_x4(a[im], base + (uint32_t)(rowA + im * 16) * ROWB + koffA);
#pragma unroll
        for (int jp = 0; jp < 4; jp++)
            ldsm_x4(b[jp], bb + (uint32_t)(rowB + jp * 16) * ROWB + koffB);
    };
    auto mma_all = [&](uint32_t a[4][4], uint32_t b[4][4]) {
#pragma unroll
        for (int im = 0; im < 4; im++)
#pragma unroll
            for (int jn = 0; jn < 8; jn++)
                mma_f16(c[im][jn], a[im], &b[jn >> 1][(jn & 1) * 2]);
    };

    // prologue: prefetch 3 stages (+ fused rowsum for MODE 2)
    tile_load(0, 0);
    tile_load(1, 32);
    tile_load(2, 64);
    if (MODE == 2) {
        // 1/rowsum for this CTA's 128 rows, from g_partial (same order as before)
        const float4* p = (const float4*)(g_partial + ((size_t)z * S_ + m0 + tid) * 32);
        float s = 0.f;
#pragma unroll
        for (int i = 0; i < 8; i++) {
            float4 v = p[i];
            s += (v.x + v.y) + (v.z + v.w);
        }
        sh_inv[tid] = 1.0f / s;
    }
    CP_WAIT1();                              // stages 0,1 landed
    __syncthreads();                         // ...and visible (sh_inv too)
    ld_frags(sbase, 0, a0, b0);              // stage 0 kf0

    for (int i = 0; i < TI; i++) {
        uint32_t s0 = sbase + (uint32_t)((2 * i) % STG) * STGBYTES;
        uint32_t s1 = sbase + (uint32_t)((2 * i + 1) % STG) * STGBYTES;
        ld_frags(s0, 1, a1, b1);             // s0 kf1 (s0,s1 visible: prev barrier)
        {                                    // exactly two commits per iteration
            int tn = 2 * i + 3;
            if (tn < NST) tile_load(tn % STG, tn * 32); else CP_COMMIT();
            tn = 2 * i + 4;
            if (tn < NST) tile_load(tn % STG, tn * 32); else CP_COMMIT();
        }
        mma_all(a0, b0);                     // s0 kf0
        ld_frags(s1, 0, a0, b0);             // s1 kf0
        mma_all(a1, b1);                     // s0 kf1
        ld_frags(s1, 1, a1, b1);             // s1 kf1
        mma_all(a0, b0);                     // s1 kf0
        CP_WAIT1();                          // stages <= 2i+3 landed (this thread)
        __syncthreads();                     // ...and visible from ALL threads
        if (i + 1 < TI) {
            uint32_t ns0 = sbase + (uint32_t)((2 * i + 2) % STG) * STGBYTES;
            ld_frags(ns0, 0, a0, b0);        // next iteration's s0 kf0
        }
        mma_all(a1, b1);                     // s1 kf1
    }
    __syncthreads();

    // ---- epilogue ----
    float rs[4][2];
    if (MODE == 1) {
#pragma unroll
        for (int i = 0; i < 4; i++) { rs[i][0] = 0.f; rs[i][1] = 0.f; }
    }

    if (MODE == 0 && which == 2) {
        // V branch: smem-transpose the 128x128 tile, store coalesced to g_vt[z][d][s]
#pragma unroll
        for (int im = 0; im < 4; im++) {
#pragma unroll
            for (int jn = 0; jn < 8; jn++) {
                int r0l = warp_m * 64 + im * 16 + (lane >> 2);
                int ccl = warp_n * 64 + jn * 8 + (lane & 3) * 2;
                float2 bv = *(const float2*)&bias[n0 + ccl];
                sh[ccl * 136 + r0l]           = __float2half_rn(c[im][jn][0] + bv.x);
                sh[(ccl + 1) * 136 + r0l]     = __float2half_rn(c[im][jn][1] + bv.y);
                sh[ccl * 136 + r0l + 8]       = __float2half_rn(c[im][jn][2] + bv.x);
                sh[(ccl + 1) * 136 + r0l + 8] = __float2half_rn(c[im][jn][3] + bv.y);
            }
        }
        __syncthreads();
        int ccg = n0 + tid;                          // global column (d-dim)
        int h = ccg >> 9, dd = ccg & 511;
        int b = m0 >> 11, s0 = m0 & 2047;
        float4* dst = (float4*)(g_vt + ((size_t)(b * 8 + h) * D_ + dd) * S_ + s0);
        const float4* src = (const float4*)(sh + (size_t)tid * 136);
#pragma unroll
        for (int i = 0; i < 16; i++) dst[i] = src[i];
        return;
    }

#pragma unroll
    for (int im = 0; im < 4; im++) {
#pragma unroll
        for (int jn = 0; jn < 8; jn++) {
            int r0 = m0 + warp_m * 64 + im * 16 + (lane >> 2);
            int cc = n0 + warp_n * 64 + jn * 8 + (lane & 3) * 2;
            float2 lo = make_float2(c[im][jn][0], c[im][jn][1]);
            float2 hi = make_float2(c[im][jn][2], c[im][jn][3]);

            if (MODE == 0) {
                float2 bv = *(const float2*)&bias[cc];
                lo.x += bv.x; lo.y += bv.y;
                hi.x += bv.x; hi.y += bv.y;
                if (which == 0) {   // pre-scale Q
                    lo.x *= ATT_SCALE; lo.y *= ATT_SCALE;
                    hi.x *= ATT_SCALE; hi.y *= ATT_SCALE;
                }
                __half* C = (which == 0) ? g_q : g_k;
                int h = cc >> 9, d = cc & 511;
                int b0_ = r0 >> 11, s0 = r0 & 2047;
                *(__half2*)(C + ((size_t)(b0_ * 8 + h) * S_ + s0) * D_ + d) =
                    __floats2half2_rn(lo.x, lo.y);
                int b1_ = (r0 + 8) >> 11, s1 = (r0 + 8) & 2047;
                *(__half2*)(C + ((size_t)(b1_ * 8 + h) * S_ + s1) * D_ + d) =
                    __floats2half2_rn(hi.x, hi.y);
            } else if (MODE == 1) {
                // unnormalized softmax numerator: exp(logit), fp16 store
                float e0 = __expf(lo.x), e1 = __expf(lo.y);
                float e2 = __expf(hi.x), e3 = __expf(hi.y);
                rs[im][0] += e0 + e1;
                rs[im][1] += e2 + e3;
                __half* base = g_p + ((size_t)z << 22) + cc;
                *(__half2*)(base + (size_t)r0 * S_) = __floats2half2_rn(e0, e1);
                *(__half2*)(base + (size_t)(r0 + 8) * S_) = __floats2half2_rn(e2, e3);
            } else if (MODE == 2) {
                int r0l = r0 - m0;
                float inv0 = sh_inv[r0l];
                float inv1 = sh_inv[r0l + 8];
                lo.x *= inv0; lo.y *= inv0;
                hi.x *= inv1; hi.y *= inv1;
                int b = z >> 3, h = z & 7;
                __half* base = g_attn + (size_t)(b * S_) * DH + h * 512 + cc;
                *(__half2*)(base + (size_t)r0 * DH) = __floats2half2_rn(lo.x, lo.y);
                *(__half2*)(base + (size_t)(r0 + 8) * DH) = __floats2half2_rn(hi.x, hi.y);
            } else {
                float2 bv = *(const float2*)&bias[cc];
                lo.x += bv.x; lo.y += bv.y;
                hi.x += bv.x; hi.y += bv.y;
                *(float2*)(Cout + (size_t)r0 * D_ + cc) = lo;
                *(float2*)(Cout + (size_t)(r0 + 8) * D_ + cc) = hi;
            }
        }
    }

    if (MODE == 1) {
        // quad-reduce: lanes sharing a row differ only in (lane & 3)
#pragma unroll
        for (int im = 0; im < 4; im++) {
#pragma unroll
            for (int h2 = 0; h2 < 2; h2++) {
                float v = rs[im][h2];
                v += __shfl_xor_sync(0xffffffffu, v, 1);
                v += __shfl_xor_sync(0xffffffffu, v, 2);
                if ((lane & 3) == 0) {
                    int grow = m0 + warp_m * 64 + im * 16 + (lane >> 2) + h2 * 8;
                    g_partial[((size_t)z * S_ + grow) * 32 + (n0 >> 7) * 2 + warp_n] = v;
                }
            }
        }
    }
}

// ---------------- launch ------------------------------------------------------
extern "C" void kernel_launch(void* const* d_in, const int* in_sizes, int n_in,
                              void* d_out, int out_size) {
    const float* x    = (const float*)d_in[0];
    const float* ln_w = (const float*)d_in[1];
    const float* ln_b = (const float*)d_in[2];
    const float* q_w  = (const float*)d_in[3];
    const float* q_b  = (const float*)d_in[4];
    const float* k_w  = (const float*)d_in[5];
    const float* k_b  = (const float*)d_in[6];
    const float* v_w  = (const float*)d_in[7];
    const float* v_b  = (const float*)d_in[8];
    const float* o_w  = (const float*)d_in[9];
    const float* o_b  = (const float*)d_in[10];
    float* out = (float*)d_out;

    static bool attr_done = false;
    if (!attr_done) {
        cudaFuncSetAttribute(gemm_tc<0>, cudaFuncAttributeMaxDynamicSharedMemorySize, GEMM_SMEM);
        cudaFuncSetAttribute(gemm_tc<1>, cudaFuncAttributeMaxDynamicSharedMemorySize, GEMM_SMEM);
        cudaFuncSetAttribute(gemm_tc<2>, cudaFuncAttributeMaxDynamicSharedMemorySize, GEMM_SMEM);
        cudaFuncSetAttribute(gemm_tc<3>, cudaFuncAttributeMaxDynamicSharedMemorySize, GEMM_SMEM);
        attr_done = true;
    }

    ln_kernel<<<NT, 128>>>(x, ln_w, ln_b);
    transpose_all<<<8192, dim3(32, 8)>>>(q_w, k_w, v_w, o_w);

    // merged QKV: 3 x 2048 CTAs in one launch (which = bid >> 11); V -> g_vt direct
    gemm_tc<0><<<6144, 128, GEMM_SMEM>>>(q_b, k_b, v_b, nullptr);

    dim3 gS(S_ / 128, S_ / 128, ZN);                       // (16, 16, 32)
    gemm_tc<1><<<gS, 128, GEMM_SMEM>>>(nullptr, nullptr, nullptr, nullptr);

    dim3 gPV(D_ / 128, S_ / 128, ZN);                      // (4, 16, 32)
    gemm_tc<2><<<gPV, 128, GEMM_SMEM>>>(nullptr, nullptr, nullptr, nullptr);

    dim3 gO(D_ / 128, NT / 128, 1);                        // (4, 64)
    gemm_tc<3><<<gO, 128, GEMM_SMEM>>>(o_b, nullptr, nullptr, out);
}

// round 16
// speedup vs baseline: 1.1464x; 1.1464x over previous
#include <cuda_runtime.h>
#include <cuda_fp16.h>
#include <cstdint>

// ---------------- problem constants ------------------------------------------
#define B_ 4
#define S_ 2048
#define D_ 512
#define H_ 8
#define NT 8192               // B*S tokens
#define DH 4096               // D*H
#define ZN 32                 // B*H attention instances
#define ATT_SCALE 0.04419417382415922f   // 512^-0.5

// ---------------- scratch (device globals; no runtime allocation) -------------
__device__ __half g_xn[(size_t)NT * D_];               // 8 MB
__device__ __half g_q[(size_t)ZN * S_ * D_];           // 64 MB [z][s][d] (pre-scaled)
__device__ __half g_k[(size_t)ZN * S_ * D_];           // 64 MB [z][s][d]
__device__ __half g_vt[(size_t)ZN * S_ * D_];          // 64 MB [z][d][s]
__device__ __half g_p[(size_t)ZN * S_ * S_];           // 256 MB fp16 exp(logits)
__device__ float  g_partial[(size_t)ZN * S_ * 32];     // 8 MB per-row partial sums
__device__ __half g_attn[(size_t)NT * DH];             // 64 MB [token][h*512+d]
__device__ __half g_wtq[(size_t)DH * D_];              // 4 MB  W^T [4096][512]
__device__ __half g_wtk[(size_t)DH * D_];
__device__ __half g_wtv[(size_t)DH * D_];
__device__ __half g_wto[(size_t)D_ * DH];              // 4 MB  o_w^T [512][4096]

// ---------------- helpers -----------------------------------------------------
__device__ __forceinline__ uint32_t smem_u32(const void* p) {
    uint32_t a;
    asm("{ .reg .u64 t; cvta.to.shared.u64 t, %1; cvt.u32.u64 %0, t; }" : "=r"(a) : "l"(p));
    return a;
}
__device__ __forceinline__ void cp16(uint32_t dst, const void* src) {
    asm volatile("cp.async.cg.shared.global [%0], [%1], 16;" :: "r"(dst), "l"(src));
}
#define CP_COMMIT() asm volatile("cp.async.commit_group;")
#define CP_WAIT2()  asm volatile("cp.async.wait_group 2;")

__device__ __forceinline__ void ldsm_x4(uint32_t* r, uint32_t addr) {
    asm volatile("ldmatrix.sync.aligned.m8n8.x4.shared.b16 {%0,%1,%2,%3}, [%4];"
        : "=r"(r[0]), "=r"(r[1]), "=r"(r[2]), "=r"(r[3]) : "r"(addr));
}
__device__ __forceinline__ void mma_f16(float* c, const uint32_t* a, const uint32_t* b) {
    asm volatile(
        "mma.sync.aligned.m16n8k16.row.col.f32.f16.f16.f32 "
        "{%0,%1,%2,%3}, {%4,%5,%6,%7}, {%8,%9}, {%0,%1,%2,%3};"
        : "+f"(c[0]), "+f"(c[1]), "+f"(c[2]), "+f"(c[3])
        : "r"(a[0]), "r"(a[1]), "r"(a[2]), "r"(a[3]), "r"(b[0]), "r"(b[1]));
}

// ---------------- LayerNorm (fp32 in -> fp16 out) -----------------------------
__global__ void ln_kernel(const float* __restrict__ x,
                          const float* __restrict__ w,
                          const float* __restrict__ b) {
    int row = blockIdx.x;
    int t = threadIdx.x;                       // 128 threads, 4 floats each
    const float4* xr = (const float4*)(x + (size_t)row * D_);
    float4 v = xr[t];
    float s  = v.x + v.y + v.z + v.w;
    float q  = v.x * v.x + v.y * v.y + v.z * v.z + v.w * v.w;
#pragma unroll
    for (int o = 16; o > 0; o >>= 1) {
        s += __shfl_xor_sync(0xffffffffu, s, o);
        q += __shfl_xor_sync(0xffffffffu, q, o);
    }
    __shared__ float ss[4], sq[4];
    int wid = t >> 5;
    if ((t & 31) == 0) { ss[wid] = s; sq[wid] = q; }
    __syncthreads();
    s = ss[0] + ss[1] + ss[2] + ss[3];
    q = sq[0] + sq[1] + sq[2] + sq[3];
    float mu  = s * (1.0f / D_);
    float var = q * (1.0f / D_) - mu * mu;
    float r   = rsqrtf(var + 1e-5f);
    float4 wv = ((const float4*)w)[t];
    float4 bv = ((const float4*)b)[t];
    __half2 h0 = __floats2half2_rn((v.x - mu) * r * wv.x + bv.x,
                                   (v.y - mu) * r * wv.y + bv.y);
    __half2 h1 = __floats2half2_rn((v.z - mu) * r * wv.z + bv.z,
                                   (v.w - mu) * r * wv.w + bv.w);
    __half2* dst = (__half2*)(g_xn + (size_t)row * D_);
    dst[2 * t]     = h0;
    dst[2 * t + 1] = h1;
}

// ---------------- merged 32x32 weight transposes (fp32 in -> half out) --------
__global__ void transpose_all(const float* __restrict__ qw, const float* __restrict__ kw,
                              const float* __restrict__ vw, const float* __restrict__ ow) {
    __shared__ float tile[32][33];
    int sel = blockIdx.x >> 11;                  // 0..3
    int id  = blockIdx.x & 2047;
    const float* in;
    __half* out;
    int R, C, bx, by;
    if (sel < 3) {
        in = (sel == 0) ? qw : (sel == 1) ? kw : vw;
        out = (sel == 0) ? g_wtq : (sel == 1) ? g_wtk : g_wtv;
        R = 512; C = 4096;
        bx = id & 127; by = id >> 7;             // 128 x 16
    } else {
        in = ow; out = g_wto;
        R = 4096; C = 512;
        bx = id & 15; by = id >> 4;              // 16 x 128
    }

    int x  = bx * 32 + threadIdx.x;
    int y0 = by * 32;
#pragma unroll
    for (int j = 0; j < 32; j += 8)
        tile[threadIdx.y + j][threadIdx.x] = in[(size_t)(y0 + threadIdx.y + j) * C + x];
    __syncthreads();
    int ox  = y0 + threadIdx.x;
    int oy0 = bx * 32;
#pragma unroll
    for (int j = 0; j < 32; j += 8)
        out[(size_t)(oy0 + threadIdx.y + j) * R + ox] =
            __float2half_rn(tile[threadIdx.x][threadIdx.y + j]);
}

// ---------------- fp16 mma.sync GEMM ------------------------------------------
// 128x128 CTA tile, 128 threads = 4 warps (2x2), warp tile 64x64.
// BK=32, 4-stage cp.async pipeline (R14's proven loop), double-buffered frags,
// ONE __syncthreads per k-tile. Half-precision outputs are STAGED through SMEM
// and written out as coalesced 256B rows (full-sector stores).
// MODE 0: g_xn @ Wt(which)^T -> q(/scale)/k half (staged); V -> g_vt direct
// MODE 1: Qs @ K^T -> exp -> g_p (staged) + row partial sums (per z)
// MODE 2: E @ Vt^T * (1/rowsum, prologue-fused) -> g_attn (staged)
// MODE 3: g_attn @ Wto^T -> out fp32 (+bias), direct (already full-sector)
constexpr int STG = 4;
constexpr int ROWB = 80;                         // 32 halves (64B) + 16B pad
constexpr int OPBYTES = 128 * ROWB;              // one operand tile: 10240 B
constexpr int STGBYTES = 2 * OPBYTES;            // A+B per stage: 20480 B
constexpr int PIPEBYTES = STG * STGBYTES;        // 81920 B
constexpr int GEMM_SMEM = PIPEBYTES + 512;       // + sh_inv[128] for MODE 2

template <int MODE>
__global__ __launch_bounds__(128, 2)
void gemm_tc(const float* __restrict__ bias0, const float* __restrict__ bias1,
             const float* __restrict__ bias2, float* __restrict__ Cout) {
    constexpr int K   = (MODE == 0) ? 512 : (MODE == 1) ? 512 : (MODE == 2) ? 2048 : 4096;
    constexpr int lda = (MODE == 2) ? 2048 : (MODE == 3) ? 4096 : 512;
    constexpr int ldb = (MODE == 2) ? 2048 : (MODE == 3) ? 4096 : 512;
    constexpr int T   = K / 32;

    extern __shared__ __half sh[];
    uint32_t sbase = smem_u32(sh);
    float* sh_inv = (float*)((char*)sh + PIPEBYTES);

    int tid = threadIdx.x;
    int lane = tid & 31, wid = tid >> 5;       // 4 warps
    int warp_m = wid & 1, warp_n = wid >> 1;   // 2 x 2 -> 64 x 64 per warp

    int which = 0, m0, n0, z = 0;
    if (MODE == 0) {                 // merged QKV: 1D grid of 6144
        which = blockIdx.x >> 11;
        int id = blockIdx.x & 2047;
        n0 = (id & 31) * 128;
        m0 = (id >> 5) * 128;
    } else {
        n0 = blockIdx.x * 128;
        m0 = blockIdx.y * 128;
        z  = blockIdx.z;
    }
    const float* bias = (MODE == 0)
        ? (which == 0 ? bias0 : which == 1 ? bias1 : bias2) : bias0;

    const __half* A;
    const __half* Bm;
    if (MODE == 0)      { A = g_xn;
                          Bm = (which == 0) ? g_wtq : (which == 1) ? g_wtk : g_wtv; }
    else if (MODE == 1) { A = g_q + (size_t)z * S_ * D_; Bm = g_k + (size_t)z * S_ * D_; }
    else if (MODE == 2) { A = g_p + ((size_t)z << 22);   Bm = g_vt + (size_t)z * S_ * D_; }
    else                { A = g_attn; Bm = g_wto; }
    A  += (size_t)m0 * lda;
    Bm += (size_t)n0 * ldb;

    float c[4][8][4];
#pragma unroll
    for (int i = 0; i < 4; i++)
#pragma unroll
        for (int j = 0; j < 8; j++)
#pragma unroll
            for (int e = 0; e < 4; e++) c[i][j][e] = 0.0f;

    // tile fill: 128 rows x 32 halves per operand = 512 x 16B each; 4+4 per thread
    int lrow = tid >> 2, lseg = tid & 3;       // lrow 0..31
    auto tile_load = [&](int stg, int k0) {
        uint32_t abase = sbase + (uint32_t)stg * STGBYTES;
        uint32_t bbase = abase + OPBYTES;
        uint32_t off = (uint32_t)lrow * ROWB + (uint32_t)lseg * 16;
#pragma unroll
        for (int i = 0; i < 4; i++) {
            cp16(abase + off + (uint32_t)i * 32 * ROWB,
                 A + (size_t)(lrow + i * 32) * lda + k0 + lseg * 8);
            cp16(bbase + off + (uint32_t)i * 32 * ROWB,
                 Bm + (size_t)(lrow + i * 32) * ldb + k0 + lseg * 8);
        }
        CP_COMMIT();
    };

    // ldmatrix lane geometry
    int rowA = warp_m * 64 + (lane & 7) + ((lane & 8) ? 8 : 0);
    int kA   = (lane & 16) ? 8 : 0;
    int rowB = warp_n * 64 + (lane & 7) + ((lane & 16) ? 8 : 0);
    int kB   = (lane & 8) ? 8 : 0;

    uint32_t a0[4][4], b0[4][4], a1[4][4], b1[4][4];   // double-buffered frags

    auto ld_frags = [&](uint32_t base, int kf, uint32_t a[4][4], uint32_t b[4][4]) {
        uint32_t koffA = (uint32_t)(kA + kf * 16) * 2;
        uint32_t koffB = (uint32_t)(kB + kf * 16) * 2;
        uint32_t bb = base + OPBYTES;
#pragma unroll
        for (int im = 0; im < 4; im++)
            ldsm_x4(a[im], base + (uint32_t)(rowA + im * 16) * ROWB + koffA);
#pragma unroll
        for (int jp = 0; jp < 4; jp++)
            ldsm_x4(b[jp], bb + (uint32_t)(rowB + jp * 16) * ROWB + koffB);
    };
    auto mma_all = [&](uint32_t a[4][4], uint32_t b[4][4]) {
#pragma unroll
        for (int im = 0; im < 4; im++)
#pragma unroll
            for (int jn = 0; jn < 8; jn++)
                mma_f16(c[im][jn], a[im], &b[jn >> 1][(jn & 1) * 2]);
    };

    // prologue: prefetch STG-1 tiles (+ fused rowsum for MODE 2)
    tile_load(0, 0);
    tile_load(1, 32);
    tile_load(2, 64);
    if (MODE == 2) {
        // 1/rowsum for this CTA's 128 rows, from g_partial (same order as before)
        const float4* p = (const float4*)(g_partial + ((size_t)z * S_ + m0 + tid) * 32);
        float s = 0.f;
#pragma unroll
        for (int i = 0; i < 8; i++) {
            float4 v = p[i];
            s += (v.x + v.y) + (v.z + v.w);
        }
        sh_inv[tid] = 1.0f / s;
    }
    CP_WAIT2();
    __syncthreads();                         // stage 0 (and sh_inv) visible
    ld_frags(sbase, 0, a0, b0);

    for (int t = 0; t < T; t++) {
        uint32_t abase = sbase + (uint32_t)(t % STG) * STGBYTES;
        ld_frags(abase, 1, a1, b1);          // stage t kf=1 frags (visible: barrier t-1)
        {
            int tn = t + STG - 1;            // overwrites stage (t-1)%STG; reads of it
            if (tn < T) tile_load(tn % STG, tn * 32);   // ended before barrier t-1
            else        CP_COMMIT();         // empty group keeps wait count aligned
        }
        mma_all(a0, b0);                     // kf=0 math
        CP_WAIT2();                          // stage t+1 landed (this thread)
        __syncthreads();                     // ...and visible from ALL threads
        uint32_t nbase = sbase + (uint32_t)((t + 1) % STG) * STGBYTES;
        ld_frags(nbase, 0, a0, b0);          // next tile kf=0 frags (stale at t=T-1: unused)
        mma_all(a1, b1);                     // kf=1 math
    }
    __syncthreads();

    // ---- epilogue ----
    float rs[4][2];
    if (MODE == 1) {
#pragma unroll
        for (int i = 0; i < 4; i++) { rs[i][0] = 0.f; rs[i][1] = 0.f; }
    }

    if (MODE == 0 && which == 2) {
        // V branch: smem-transpose the 128x128 tile, store coalesced to g_vt[z][d][s]
#pragma unroll
        for (int im = 0; im < 4; im++) {
#pragma unroll
            for (int jn = 0; jn < 8; jn++) {
                int r0l = warp_m * 64 + im * 16 + (lane >> 2);
                int ccl = warp_n * 64 + jn * 8 + (lane & 3) * 2;
                float2 bv = *(const float2*)&bias[n0 + ccl];
                sh[ccl * 136 + r0l]           = __float2half_rn(c[im][jn][0] + bv.x);
                sh[(ccl + 1) * 136 + r0l]     = __float2half_rn(c[im][jn][1] + bv.y);
                sh[ccl * 136 + r0l + 8]       = __float2half_rn(c[im][jn][2] + bv.x);
                sh[(ccl + 1) * 136 + r0l + 8] = __float2half_rn(c[im][jn][3] + bv.y);
            }
        }
        __syncthreads();
        int ccg = n0 + tid;                          // global column (d-dim)
        int h = ccg >> 9, dd = ccg & 511;
        int b = m0 >> 11, s0 = m0 & 2047;
        float4* dst = (float4*)(g_vt + ((size_t)(b * 8 + h) * D_ + dd) * S_ + s0);
        const float4* src = (const float4*)(sh + (size_t)tid * 136);
#pragma unroll
        for (int i = 0; i < 16; i++) dst[i] = src[i];
        return;
    }

    if (MODE == 3) {
        // fp32 output, float2 stores = full 32B sectors already
#pragma unroll
        for (int im = 0; im < 4; im++) {
#pragma unroll
            for (int jn = 0; jn < 8; jn++) {
                int r0 = m0 + warp_m * 64 + im * 16 + (lane >> 2);
                int cc = n0 + warp_n * 64 + jn * 8 + (lane & 3) * 2;
                float2 bv = *(const float2*)&bias[cc];
                float2 lo = make_float2(c[im][jn][0] + bv.x, c[im][jn][1] + bv.y);
                float2 hi = make_float2(c[im][jn][2] + bv.x, c[im][jn][3] + bv.y);
                *(float2*)(Cout + (size_t)r0 * D_ + cc) = lo;
                *(float2*)(Cout + (size_t)(r0 + 8) * D_ + cc) = hi;
            }
        }
        return;
    }

    // ---- staged half-precision epilogue (MODE 0 Q/K, MODE 1, MODE 2) ----
    // stage tile at sh[row][col], row stride 136 halves (conflict-free writes)
#pragma unroll
    for (int im = 0; im < 4; im++) {
#pragma unroll
        for (int jn = 0; jn < 8; jn++) {
            int r0l = warp_m * 64 + im * 16 + (lane >> 2);
            int ccl = warp_n * 64 + jn * 8 + (lane & 3) * 2;
            float2 lo = make_float2(c[im][jn][0], c[im][jn][1]);
            float2 hi = make_float2(c[im][jn][2], c[im][jn][3]);

            if (MODE == 0) {
                float2 bv = *(const float2*)&bias[n0 + ccl];
                lo.x += bv.x; lo.y += bv.y;
                hi.x += bv.x; hi.y += bv.y;
                if (which == 0) {
                    lo.x *= ATT_SCALE; lo.y *= ATT_SCALE;
                    hi.x *= ATT_SCALE; hi.y *= ATT_SCALE;
                }
            } else if (MODE == 1) {
                lo.x = __expf(lo.x); lo.y = __expf(lo.y);
                hi.x = __expf(hi.x); hi.y = __expf(hi.y);
                rs[im][0] += lo.x + lo.y;
                rs[im][1] += hi.x + hi.y;
            } else {  // MODE 2
                float inv0 = sh_inv[r0l];
                float inv1 = sh_inv[r0l + 8];
                lo.x *= inv0; lo.y *= inv0;
                hi.x *= inv1; hi.y *= inv1;
            }
            *(__half2*)(sh + (size_t)r0l * 136 + ccl) = __floats2half2_rn(lo.x, lo.y);
            *(__half2*)(sh + (size_t)(r0l + 8) * 136 + ccl) = __floats2half2_rn(hi.x, hi.y);
        }
    }
    __syncthreads();

    // coalesced writeout: 128 rows x 256B; lanes 0-15 cover one full row segment
    {
        const __half* gbase;
        size_t ldc;
        if (MODE == 0) {
            __half* C = (which == 0) ? g_q : g_k;
            int b = m0 >> 11, s0 = m0 & 2047;
            int h = n0 >> 9, d0 = n0 & 511;
            gbase = C + ((size_t)(b * 8 + h) * S_ + s0) * D_ + d0;
            ldc = D_;
        } else if (MODE == 1) {
            gbase = g_p + ((size_t)z << 22) + (size_t)m0 * S_ + n0;
            ldc = S_;
        } else {
            int b = z >> 3, h = z & 7;
            gbase = g_attn + ((size_t)(b * S_ + m0)) * DH + h * 512 + n0;
            ldc = DH;
        }
#pragma unroll
        for (int i = 0; i < 16; i++) {
            int idx = tid + (i << 7);
            int row = idx >> 4, seg = idx & 15;
            *(float4*)((__half*)gbase + (size_t)row * ldc + seg * 8) =
                *(const float4*)(sh + (size_t)row * 136 + seg * 8);
        }
    }

    if (MODE == 1) {
        // quad-reduce: lanes sharing a row differ only in (lane & 3)
#pragma unroll
        for (int im = 0; im < 4; im++) {
#pragma unroll
            for (int h2 = 0; h2 < 2; h2++) {
                float v = rs[im][h2];
                v += __shfl_xor_sync(0xffffffffu, v, 1);
                v += __shfl_xor_sync(0xffffffffu, v, 2);
                if ((lane & 3) == 0) {
                    int grow = m0 + warp_m * 64 + im * 16 + (lane >> 2) + h2 * 8;
                    g_partial[((size_t)z * S_ + grow) * 32 + (n0 >> 7) * 2 + warp_n] = v;
                }
            }
        }
    }
}

// ---------------- launch ------------------------------------------------------
extern "C" void kernel_launch(void* const* d_in, const int* in_sizes, int n_in,
                              void* d_out, int out_size) {
    const float* x    = (const float*)d_in[0];
    const float* ln_w = (const float*)d_in[1];
    const float* ln_b = (const float*)d_in[2];
    const float* q_w  = (const float*)d_in[3];
    const float* q_b  = (const float*)d_in[4];
    const float* k_w  = (const float*)d_in[5];
    const float* k_b  = (const float*)d_in[6];
    const float* v_w  = (const float*)d_in[7];
    const float* v_b  = (const float*)d_in[8];
    const float* o_w  = (const float*)d_in[9];
    const float* o_b  = (const float*)d_in[10];
    float* out = (float*)d_out;

    static bool attr_done = false;
    if (!attr_done) {
        cudaFuncSetAttribute(gemm_tc<0>, cudaFuncAttributeMaxDynamicSharedMemorySize, GEMM_SMEM);
        cudaFuncSetAttribute(gemm_tc<1>, cudaFuncAttributeMaxDynamicSharedMemorySize, GEMM_SMEM);
        cudaFuncSetAttribute(gemm_tc<2>, cudaFuncAttributeMaxDynamicSharedMemorySize, GEMM_SMEM);
        cudaFuncSetAttribute(gemm_tc<3>, cudaFuncAttributeMaxDynamicSharedMemorySize, GEMM_SMEM);
        attr_done = true;
    }

    ln_kernel<<<NT, 128>>>(x, ln_w, ln_b);
    transpose_all<<<8192, dim3(32, 8)>>>(q_w, k_w, v_w, o_w);

    // merged QKV: 3 x 2048 CTAs in one launch (which = bid >> 11); V -> g_vt direct
    gemm_tc<0><<<6144, 128, GEMM_SMEM>>>(q_b, k_b, v_b, nullptr);

    dim3 gS(S_ / 128, S_ / 128, ZN);                       // (16, 16, 32)
    gemm_tc<1><<<gS, 128, GEMM_SMEM>>>(nullptr, nullptr, nullptr, nullptr);

    dim3 gPV(D_ / 128, S_ / 128, ZN);                      // (4, 16, 32)
    gemm_tc<2><<<gPV, 128, GEMM_SMEM>>>(nullptr, nullptr, nullptr, nullptr);

    dim3 gO(D_ / 128, NT / 128, 1);                        // (4, 64)
    gemm_tc<3><<<gO, 128, GEMM_SMEM>>>(o_b, nullptr, nullptr, out);
}